// round 5
// baseline (speedup 1.0000x reference)
#include <cuda_runtime.h>
#include <cstdint>

// Problem constants: B=16, S=4096, D=64, K=4096
#define D_DIM     64
#define K_CODES   4096
#define N_ROWS    65536               // B*S
#define ROWS_CTA  64
#define THREADS   128
#define CHUNK     128                 // codes per smem chunk
#define N_CHUNKS  (K_CODES / CHUNK)   // 32
#define N_BLOCKS  (N_ROWS / ROWS_CTA) // 1024
#define NQ_ELEMS  (N_ROWS * D_DIM)    // 4194304
#define ZSTRIDE   66                  // zdup row stride in float2 (16B-aligned rows)

// Device-global scratch (no allocations allowed)
__device__ float  g_embT[D_DIM * K_CODES];   // transposed codebook [d][k]
__device__ float  g_ee[K_CODES];             // ||e_k||^2, serial fp32
__device__ double g_lossPart[N_BLOCKS];      // per-CTA loss partials

__device__ __forceinline__ uint32_t smem_u32(const void* p) {
    return (uint32_t)__cvta_generic_to_shared(p);
}

#define CP16(dst, src) \
    asm volatile("cp.async.cg.shared.global [%0], [%1], 16;" :: "r"(dst), "l"(src))

__device__ __forceinline__ unsigned long long u64lo(const float4& v) {
    return *reinterpret_cast<const unsigned long long*>(&v.x);
}
__device__ __forceinline__ unsigned long long u64hi(const float4& v) {
    return *reinterpret_cast<const unsigned long long*>(&v.z);
}

struct __align__(16) Smem {
    float  e[2][D_DIM * CHUNK];       //  65536 B : embT chunk [d][c], dbl buffered
    float  ee[2][CHUNK];              //   1024 B
    float2 zdup[ROWS_CTA * ZSTRIDE];  //  33792 B : (2z,2z) per (row,d)
    float  zz[ROWS_CTA];              //    256 B
    float  redV[ROWS_CTA * 16];       //   4096 B
    int    redI[ROWS_CTA * 16];       //   4096 B
    double lossBuf[ROWS_CTA];         //    512 B
};                                    // 109312 B -> occupancy 2

// ---------------------------------------------------------------------------
// Prep: smem-tiled transpose + ||e||^2 serial chain
// ---------------------------------------------------------------------------
__global__ void vq_prep(const float* __restrict__ emb) {
    __shared__ float tile[32][D_DIM + 1];
    const int tid = threadIdx.x;             // 256 threads
    const int k0  = blockIdx.x * 32;

    #pragma unroll
    for (int it = 0; it < 8; ++it) {
        int i = tid + it * 256;
        int kl = i >> 6, d = i & 63;
        tile[kl][d] = __ldg(&emb[(size_t)(k0 + kl) * D_DIM + d]);
    }
    __syncthreads();

    #pragma unroll
    for (int it = 0; it < 8; ++it) {
        int i = tid + it * 256;
        int d = i >> 5, kl = i & 31;
        g_embT[(size_t)d * K_CODES + k0 + kl] = tile[kl][d];
    }

    if (tid < 32) {
        float s = 0.0f;
        #pragma unroll
        for (int d = 0; d < D_DIM; ++d) {
            float v = tile[tid][d];
            s = __fadd_rn(s, __fmul_rn(v, v));
        }
        g_ee[k0 + tid] = s;
    }
}

// ---------------------------------------------------------------------------
// Main kernel
// ---------------------------------------------------------------------------
__device__ __forceinline__ void load_chunk(Smem& sm, int buf, int chunk, int tid) {
    uint32_t eBase = smem_u32(&sm.e[buf][0]);
    #pragma unroll
    for (int it = 0; it < 16; ++it) {
        int i   = tid + it * THREADS;        // 0..2047
        int d   = i >> 5;
        int seg = i & 31;
        uint32_t dst = eBase + (uint32_t)(d * CHUNK + seg * 4) * 4u;
        const float* s = g_embT + (size_t)d * K_CODES + chunk * CHUNK + seg * 4;
        CP16(dst, s);
    }
    if (tid < 32) {
        uint32_t dst = smem_u32(&sm.ee[buf][0]) + tid * 16;
        const float* s = g_ee + chunk * CHUNK + tid * 4;
        CP16(dst, s);
    }
    asm volatile("cp.async.commit_group;" ::: "memory");
}

__global__ void __launch_bounds__(THREADS, 2)
vq_main(const float* __restrict__ z, const float* __restrict__ emb,
        float* __restrict__ out)
{
    extern __shared__ unsigned char smraw[];
    Smem& sm = *reinterpret_cast<Smem*>(smraw);

    const int tid = threadIdx.x;
    const int tc  = tid & 15;     // code lane 0..15 (4 consecutive codes per group)
    const int tr  = tid >> 4;     // row group 0..7 (8 rows each)
    const int rowBase = blockIdx.x * ROWS_CTA;

    // ---- load z tile, store duplicated (2z,2z); 2z exact ----
    const float4* zg = reinterpret_cast<const float4*>(z + (size_t)rowBase * D_DIM);
    #pragma unroll
    for (int it = 0; it < 8; ++it) {
        int q = tid + it * THREADS;          // 0..1023 float4s
        float4 v = zg[q];
        int row = q >> 4;
        int c   = (q & 15) << 2;
        float2* p = &sm.zdup[row * ZSTRIDE + c];
        p[0] = make_float2(v.x + v.x, v.x + v.x);
        p[1] = make_float2(v.y + v.y, v.y + v.y);
        p[2] = make_float2(v.z + v.z, v.z + v.z);
        p[3] = make_float2(v.w + v.w, v.w + v.w);
    }
    __syncthreads();

    // ---- zz per row: serial fl(s + fl(z*z)) ----
    if (tid < ROWS_CTA) {
        float s = 0.0f;
        const float2* zr = &sm.zdup[tid * ZSTRIDE];
        #pragma unroll
        for (int d = 0; d < D_DIM; ++d) {
            float zv = 0.5f * zr[d].x;       // exact recovery of z
            s = __fadd_rn(s, __fmul_rn(zv, zv));
        }
        sm.zz[tid] = s;
    }
    __syncthreads();

    float rzz[8];
    #pragma unroll
    for (int i = 0; i < 8; ++i) rzz[i] = sm.zz[tr * 8 + i];

    float bestV[8];
    int   bestI[8];
    #pragma unroll
    for (int i = 0; i < 8; ++i) { bestV[i] = 3.402823466e38f; bestI[i] = 0; }

    load_chunk(sm, 0, 0, tid);
    asm volatile("cp.async.wait_group 0;" ::: "memory");
    __syncthreads();

    // float4 views: zrow4[i*33 + d2] = (2z,2z) for d=2*d2 and 2*d2+1 of row i
    const float4* zrow4 =
        reinterpret_cast<const float4*>(&sm.zdup[tr * 8 * ZSTRIDE]);

    for (int c = 0; c < N_CHUNKS; ++c) {
        const int buf = c & 1;
        if (c + 1 < N_CHUNKS) load_chunk(sm, (c + 1) & 1, c + 1, tid);

        // acc[i][j]: j0=(4tc,4tc+1) j1=(4tc+2,4tc+3) j2=(64+4tc,..) j3=(64+4tc+2,..)
        unsigned long long acc[8][4];
        #pragma unroll
        for (int i = 0; i < 8; ++i)
            #pragma unroll
            for (int j = 0; j < 4; ++j) acc[i][j] = 0ull;

        const float4* eb4 = reinterpret_cast<const float4*>(&sm.e[buf][0]);
        #pragma unroll 2
        for (int d2 = 0; d2 < D_DIM / 2; ++d2) {
            float4 zA[8];
            #pragma unroll
            for (int i = 0; i < 8; ++i) zA[i] = zrow4[i * 33 + d2];
            float4 ea0 = eb4[(2 * d2)     * 32 + tc];        // d even, codes 4tc..4tc+3
            float4 ea1 = eb4[(2 * d2)     * 32 + 16 + tc];   // d even, codes 64+4tc..
            float4 eo0 = eb4[(2 * d2 + 1) * 32 + tc];        // d odd
            float4 eo1 = eb4[(2 * d2 + 1) * 32 + 16 + tc];

            unsigned long long ea[4] = { u64lo(ea0), u64hi(ea0), u64lo(ea1), u64hi(ea1) };
            unsigned long long eo[4] = { u64lo(eo0), u64hi(eo0), u64lo(eo1), u64hi(eo1) };

            #pragma unroll
            for (int i = 0; i < 8; ++i) {
                unsigned long long zlo = u64lo(zA[i]);   // d = 2*d2
                unsigned long long zhi = u64hi(zA[i]);   // d = 2*d2+1
                #pragma unroll
                for (int j = 0; j < 4; ++j)
                    asm("fma.rn.f32x2 %0, %1, %2, %0;"
                        : "+l"(acc[i][j]) : "l"(zlo), "l"(ea[j]));
                #pragma unroll
                for (int j = 0; j < 4; ++j)
                    asm("fma.rn.f32x2 %0, %1, %2, %0;"
                        : "+l"(acc[i][j]) : "l"(zhi), "l"(eo[j]));
            }
        }

        // dist = fl(fl(zz+ee) - dot), strict-< argmin with index tiebreak
        #pragma unroll
        for (int j = 0; j < 4; ++j) {
            const int off   = (j >> 1) * 64 + 4 * tc + (j & 1) * 2;
            const int code0 = c * CHUNK + off;
            float ee0 = sm.ee[buf][off];
            float ee1 = sm.ee[buf][off + 1];
            #pragma unroll
            for (int i = 0; i < 8; ++i) {
                unsigned int lo, hi;
                asm("mov.b64 {%0, %1}, %2;" : "=r"(lo), "=r"(hi) : "l"(acc[i][j]));
                float d0 = __fsub_rn(__fadd_rn(rzz[i], ee0), __uint_as_float(lo));
                if (d0 < bestV[i]) { bestV[i] = d0; bestI[i] = code0; }
                float d1 = __fsub_rn(__fadd_rn(rzz[i], ee1), __uint_as_float(hi));
                if (d1 < bestV[i]) { bestV[i] = d1; bestI[i] = code0 + 1; }
            }
        }

        if (c + 1 < N_CHUNKS) asm volatile("cp.async.wait_group 0;" ::: "memory");
        __syncthreads();
    }

    // ---- cross-thread argmin reduce (lexicographic (val, idx)) ----
    #pragma unroll
    for (int i = 0; i < 8; ++i) {
        sm.redV[(tr * 8 + i) * 16 + tc] = bestV[i];
        sm.redI[(tr * 8 + i) * 16 + tc] = bestI[i];
    }
    __syncthreads();

    if (tid < ROWS_CTA) {
        const int row = tid;
        float v  = sm.redV[row * 16];
        int   bi = sm.redI[row * 16];
        #pragma unroll
        for (int t = 1; t < 16; ++t) {
            float vv = sm.redV[row * 16 + t];
            int   ii = sm.redI[row * 16 + t];
            if (vv < v || (vv == v && ii < bi)) { v = vv; bi = ii; }
        }
        const int gRow = rowBase + row;
        out[NQ_ELEMS + gRow] = (float)bi;          // indices as float32

        const float*  eRow = emb + (size_t)bi * D_DIM;
        const float2* zr   = &sm.zdup[row * ZSTRIDE];
        float* oRow = out + (size_t)gRow * D_DIM;
        double lpart = 0.0;
        #pragma unroll
        for (int d = 0; d < D_DIM; ++d) {
            float q    = __ldg(&eRow[d]);
            float zv   = 0.5f * zr[d].x;
            float diff = __fsub_rn(q, zv);          // fl(q - z)
            oRow[d]    = __fadd_rn(zv, diff);       // quantized_st
            lpart += (double)__fmul_rn(diff, diff);
        }
        sm.lossBuf[row] = lpart;
    }
    __syncthreads();

    if (tid == 0) {
        double s = 0.0;
        #pragma unroll
        for (int r = 0; r < ROWS_CTA; ++r) s += sm.lossBuf[r];  // fixed order
        g_lossPart[blockIdx.x] = s;
    }
}

// ---------------------------------------------------------------------------
// Finalize loss: deterministic tree reduction of per-CTA partials
// ---------------------------------------------------------------------------
__global__ void vq_finalize(float* __restrict__ out) {
    __shared__ double red[128];
    const int tid = threadIdx.x;                 // 128 threads
    double s = 0.0;
    #pragma unroll
    for (int i = 0; i < N_BLOCKS / 128; ++i)
        s += g_lossPart[tid * (N_BLOCKS / 128) + i];
    red[tid] = s;
    __syncthreads();
    #pragma unroll
    for (int off = 64; off > 0; off >>= 1) {
        if (tid < off) red[tid] += red[tid + off];
        __syncthreads();
    }
    if (tid == 0) {
        float m = (float)(red[0] / (double)NQ_ELEMS);
        out[NQ_ELEMS + N_ROWS] = __fadd_rn(m, m);    // vq_loss = e + q
    }
}

// ---------------------------------------------------------------------------
extern "C" void kernel_launch(void* const* d_in, const int* in_sizes, int n_in,
                              void* d_out, int out_size) {
    const float* z   = (const float*)d_in[0];   // [B,S,D]
    const float* emb = (const float*)d_in[1];   // [K,D]
    float* out = (float*)d_out;                 // [quantized | indices | loss]

    static_assert(sizeof(Smem) <= 113 * 1024, "smem too big for occ 2");
    cudaFuncSetAttribute(vq_main, cudaFuncAttributeMaxDynamicSharedMemorySize,
                         (int)sizeof(Smem));

    vq_prep<<<K_CODES / 32, 256>>>(emb);
    vq_main<<<N_BLOCKS, THREADS, sizeof(Smem)>>>(z, emb, out);
    vq_finalize<<<1, 128>>>(out);
}